// round 9
// baseline (speedup 1.0000x reference)
#include <cuda_runtime.h>

#define L_FIXED 2048
#define MAXB    16
#define EPSF    1e-8f
#define GDIM    32
#define NCELL   (GDIM * GDIM * GDIM)
#define SLOTS   24
#define GMIN    (-64.0f)
#define GINV    0.25f                    // 1 / cell_size(4.0)
#define NTHREADS 256
#define CLUSTER  8                       // CTAs per cluster = one batch (2048 atoms)

// ---- static scratch (zero-initialized at load; self-resetting each call) ----
__device__ int      g_cnt[MAXB][NCELL];
__device__ short    g_slot[MAXB][NCELL][SLOTS];
__device__ double   g_clash = 0.0;
__device__ double   g_bn    = 0.0;
__device__ double   g_bd    = 0.0;
__device__ double   g_lin   = 0.0;
__device__ double   g_S[MAXB];
__device__ unsigned g_count = 0;

__device__ __forceinline__ float warp_sum(float v) {
    #pragma unroll
    for (int off = 16; off > 0; off >>= 1)
        v += __shfl_down_sync(0xffffffffu, v, off);
    return v;
}
__device__ __forceinline__ int cell_coord(float x) {
    int c = (int)floorf((x - GMIN) * GINV);
    return min(max(c, 0), GDIM - 1);
}

// ============================================================
// One launch. grid = 8*B blocks of 256, clusters of 8 (one per batch).
//   Phase A: bin own atom + bond/stat terms     (per-thread, 1 atom)
//   cluster.sync
//   Phase B: probe 27 neighbor cells (MLP-overlapped; hits ~0.03%)
//   cluster.sync
//   Phase C: clear own cell count; last block finalizes + resets.
// ============================================================
__global__ void __launch_bounds__(NTHREADS) __cluster_dims__(CLUSTER, 1, 1)
violation_kernel(const float* __restrict__ pos,
                 const float* __restrict__ mask,
                 float* __restrict__ out, int B)
{
    const int tid  = threadIdx.x;
    const int b    = blockIdx.x / CLUSTER;            // batch = cluster id
    const int i    = (blockIdx.x % CLUSTER) * NTHREADS + tid;  // atom in batch
    const float* P = pos  + (size_t)b * L_FIXED * 3;
    const float* M = mask + (size_t)b * L_FIXED;

    __shared__ float swr[NTHREADS / 32];

    // ================= Phase A: bin + bond + stats =================
    const float mi = M[i];
    const float xi = P[3*i], yi = P[3*i+1], zi = P[3*i+2];

    float S = mi, lin = mi * mi, bn = 0.0f, bd = 0.0f;
    if (i + 1 < L_FIXED) {
        float mj = M[i + 1];
        float dx = P[3*(i+1)]   - xi;
        float dy = P[3*(i+1)+1] - yi;
        float dz = P[3*(i+1)+2] - zi;
        float d  = sqrtf(dx*dx + dy*dy + dz*dz + EPSF);
        float viol = fmaxf(fabsf(d - 3.8f) - 0.4f, 0.0f);
        float mm = mi * mj;
        bd = mm;
        bn = viol * mm;
        lin += 2.0f * mm;                         // 2*A1
    }
    if (i + 2 < L_FIXED) lin += 2.0f * mi * M[i + 2];   // 2*A2

    const int cx = cell_coord(xi), cy = cell_coord(yi), cz = cell_coord(zi);
    const int cid = (cx << 10) | (cy << 5) | cz;
    if (mi != 0.0f) {
        int s = atomicAdd(&g_cnt[b][cid], 1);
        if (s < SLOTS) g_slot[b][cid][s] = (short)i;
    }

    // block-level stat reduction + atomics (overlaps with other blocks' binning)
    {
        float v[4] = {bn, bd, lin, S};
        #pragma unroll
        for (int k = 0; k < 4; k++) {
            float w = warp_sum(v[k]);
            if ((tid & 31) == 0) swr[tid >> 5] = w;
            __syncthreads();
            if (tid == 0) {
                float s = 0.f;
                #pragma unroll
                for (int q = 0; q < NTHREADS / 32; q++) s += swr[q];
                if (s != 0.0f) {
                    if      (k == 0) atomicAdd(&g_bn,  (double)s);
                    else if (k == 1) atomicAdd(&g_bd,  (double)s);
                    else if (k == 2) atomicAdd(&g_lin, (double)s);
                    else             atomicAdd(&g_S[b], (double)s);
                }
            }
            __syncthreads();
        }
    }

    // ---- all atoms of this batch binned ----
    asm volatile("barrier.cluster.arrive.aligned;" ::: "memory");
    asm volatile("barrier.cluster.wait.aligned;"   ::: "memory");

    // ================= Phase B: 27-cell neighbor probe =================
    float acc = 0.0f;
    if (mi != 0.0f) {
        #pragma unroll
        for (int dxc = -1; dxc <= 1; dxc++) {
            #pragma unroll
            for (int dyc = -1; dyc <= 1; dyc++) {
                #pragma unroll
                for (int dzc = -1; dzc <= 1; dzc++) {
                    int nx = cx + dxc, ny = cy + dyc, nz = cz + dzc;
                    if (((unsigned)nx < GDIM) & ((unsigned)ny < GDIM) &
                        ((unsigned)nz < GDIM)) {
                        int ncid = (nx << 10) | (ny << 5) | nz;
                        int c = g_cnt[b][ncid];
                        if (c > SLOTS) c = SLOTS;
                        for (int s = 0; s < c; s++) {
                            int j = (int)g_slot[b][ncid][s];
                            int dd = j - i;
                            if (dd > 2 || dd < -2) {
                                float dx = xi - P[3*j];
                                float dy = yi - P[3*j+1];
                                float dz = zi - P[3*j+2];
                                float d2 = dx*dx + dy*dy + dz*dz;
                                if (d2 < 2.25f) {
                                    float v = fmaxf(1.5f - sqrtf(d2 + EPSF), 0.0f);
                                    acc += v * mi * M[j];
                                }
                            }
                        }
                    }
                }
            }
        }
    }
    acc = warp_sum(acc);
    if ((tid & 31) == 0) swr[tid >> 5] = acc;
    __syncthreads();
    if (tid == 0) {
        float s = 0.f;
        #pragma unroll
        for (int q = 0; q < NTHREADS / 32; q++) s += swr[q];
        if (s != 0.0f) atomicAdd(&g_clash, (double)s);
    }

    // ---- all searches of this batch done -> safe to clear its table ----
    asm volatile("barrier.cluster.arrive.aligned;" ::: "memory");
    asm volatile("barrier.cluster.wait.aligned;"   ::: "memory");

    // ================= Phase C: clear + last-block finalize =================
    g_cnt[b][cid] = 0;                       // idempotent per-cell clear

    __threadfence();
    __shared__ bool is_last;
    if (tid == 0)
        is_last = (atomicAdd(&g_count, 1u) == (unsigned)(gridDim.x - 1));
    __syncthreads();
    if (is_last && tid == 0) {
        double pd = 0.0;
        #pragma unroll
        for (int bb = 0; bb < MAXB; bb++) {
            if (bb < B) { double Sb = g_S[bb]; pd += Sb * Sb; }
        }
        pd -= g_lin;
        double bond  = g_bn / (g_bd + 1e-8);
        double clash = g_clash / (pd + 1e-8);
        out[0] = (float)bond;
        out[1] = (float)clash;
        out[2] = (float)(bond + clash);
        // reset for next graph replay
        g_clash = 0.0; g_bn = 0.0; g_bd = 0.0; g_lin = 0.0; g_count = 0u;
        #pragma unroll
        for (int bb = 0; bb < MAXB; bb++) g_S[bb] = 0.0;
    }
}

extern "C" void kernel_launch(void* const* d_in, const int* in_sizes, int n_in,
                              void* d_out, int out_size)
{
    const float* pos  = (const float*)d_in[0];
    const float* mask = (const float*)d_in[1];
    int B = in_sizes[1] / L_FIXED;
    if (B > MAXB) B = MAXB;

    violation_kernel<<<B * CLUSTER, NTHREADS>>>(pos, mask, (float*)d_out, B);
}

// round 10
// speedup vs baseline: 1.4416x; 1.4416x over previous
#include <cuda_runtime.h>

#define L_FIXED 2048
#define MAXB    16
#define EPSF    1e-8f
#define GD      20                     // cells per dim (cell = 4.0 over [-40,40))
#define NC      (GD * GD * GD)         // 8000
#define NCP     8192                   // padded for 256x32 scan
#define NTHREADS 256
#define BPB     8                      // blocks per batch (256 atoms each)

// ---- accumulators (zero at load; finalize resets for graph replay) ----
__device__ double   g_clash = 0.0;
__device__ double   g_bn    = 0.0;
__device__ double   g_bd    = 0.0;
__device__ double   g_lin   = 0.0;
__device__ double   g_S[MAXB];
__device__ unsigned g_count = 0;

__device__ __forceinline__ float warp_sum(float v) {
    #pragma unroll
    for (int off = 16; off > 0; off >>= 1)
        v += __shfl_down_sync(0xffffffffu, v, off);
    return v;
}

// clamped cell coordinate + in-cell fraction (monotone: preserves adjacency)
__device__ __forceinline__ int cell_of(float x, float &frac) {
    float u = (fminf(fmaxf(x, -40.0f), 39.996f) + 40.0f) * 0.25f;
    int c = (int)u;                      // u >= 0: truncation == floor
    frac = u - (float)c;
    return c;
}

// ============================================================
// ONE kernel, no cross-block sync. grid = 8*B blocks of 256.
// Each block: counting-sort ALL 2048 atoms of its batch into a
// shared-memory cell list (redundant across the 8 sibling blocks),
// then searches its 256 owned atoms (<=8 cells each). Last block
// (atomic ticket) finalizes and resets.
// ============================================================
__global__ void __launch_bounds__(NTHREADS)
violation_kernel(const float* __restrict__ pos,
                 const float* __restrict__ mask,
                 float* __restrict__ out, int B)
{
    const int tid = threadIdx.x;
    const int b   = blockIdx.x >> 3;
    const int i   = ((blockIdx.x & 7) << 8) + tid;      // owned atom
    const float* P = pos  + (size_t)b * L_FIXED * 3;
    const float* M = mask + (size_t)b * L_FIXED;

    __shared__ unsigned       off[NCP];                 // counts->starts->ends
    __shared__ unsigned short ids[L_FIXED];
    __shared__ unsigned       wtot[NTHREADS / 32];
    __shared__ float          swr[NTHREADS / 32];

    // zero counts (padded region included)
    #pragma unroll
    for (int c = tid; c < NCP; c += NTHREADS) off[c] = 0u;

    // ---- own atom: bond term + mask statistics (overlaps smem zeroing) ----
    const float mi = M[i];
    const float xi = P[3*i], yi = P[3*i+1], zi = P[3*i+2];
    float S = mi, lin = mi * mi, bn = 0.0f, bd = 0.0f;
    if (i + 1 < L_FIXED) {
        float mj = M[i + 1];
        float dx = P[3*(i+1)]   - xi;
        float dy = P[3*(i+1)+1] - yi;
        float dz = P[3*(i+1)+2] - zi;
        float d  = sqrtf(dx*dx + dy*dy + dz*dz + EPSF);
        float viol = fmaxf(fabsf(d - 3.8f) - 0.4f, 0.0f);
        float mm = mi * mj;
        bd = mm;
        bn = viol * mm;
        lin += 2.0f * mm;                          // 2*A1
    }
    if (i + 2 < L_FIXED) lin += 2.0f * mi * M[i + 2];   // 2*A2

    __syncthreads();

    // ---- count pass: 8 atoms per thread ----
    int mycid[BPB];
    #pragma unroll
    for (int r = 0; r < BPB; r++) {
        int a = (r << 8) + tid;
        float fx, fy, fz;
        int cx = cell_of(P[3*a],   fx);
        int cy = cell_of(P[3*a+1], fy);
        int cz = cell_of(P[3*a+2], fz);
        int cid = (cx * GD + cy) * GD + cz;
        mycid[r] = cid;
        atomicAdd(&off[cid], 1u);
    }
    __syncthreads();

    // ---- exclusive scan over 8192 counts (32 cells/thread) ----
    const int base_c = tid << 5;
    unsigned tsum = 0;
    #pragma unroll 8
    for (int c = 0; c < 32; c++) tsum += off[base_c + c];
    {
        const unsigned lane = tid & 31, w = tid >> 5;
        unsigned inc = tsum;
        #pragma unroll
        for (int d = 1; d < 32; d <<= 1) {
            unsigned n = __shfl_up_sync(0xffffffffu, inc, d);
            if (lane >= d) inc += n;
        }
        if (lane == 31) wtot[w] = inc;
        unsigned excl = inc - tsum;
        __syncthreads();
        unsigned wbase = 0;
        for (unsigned q = 0; q < w; q++) wbase += wtot[q];
        unsigned run = wbase + excl;
        #pragma unroll 8
        for (int c = 0; c < 32; c++) {
            unsigned t = off[base_c + c];
            off[base_c + c] = run;
            run += t;
        }
    }
    __syncthreads();

    // ---- scatter (off[c] becomes END of cell c; start = off[c-1]) ----
    #pragma unroll
    for (int r = 0; r < BPB; r++) {
        unsigned s = atomicAdd(&off[mycid[r]], 1u);
        ids[s] = (unsigned short)((r << 8) + tid);
    }
    __syncthreads();

    // ---- search own atom: at most 2x2x2 cells ----
    float acc = 0.0f;
    if (mi != 0.0f) {
        float fx, fy, fz;
        const int cx = cell_of(xi, fx);
        const int cy = cell_of(yi, fy);
        const int cz = cell_of(zi, fz);
        // cutoff/cell = 0.375: sphere touches one neighbor per axis at most
        const int oxr = (fx < 0.375f) ? -1 : ((fx > 0.625f) ? 1 : 0);
        const int oyr = (fy < 0.375f) ? -1 : ((fy > 0.625f) ? 1 : 0);
        const int ozr = (fz < 0.375f) ? -1 : ((fz > 0.625f) ? 1 : 0);
        const int nxl = (oxr != 0 && (unsigned)(cx + oxr) < GD) ? 2 : 1;
        const int nyl = (oyr != 0 && (unsigned)(cy + oyr) < GD) ? 2 : 1;
        const int nzl = (ozr != 0 && (unsigned)(cz + ozr) < GD) ? 2 : 1;

        for (int ax = 0; ax < nxl; ax++) {
            int nx = cx + (ax ? oxr : 0);
            for (int ay = 0; ay < nyl; ay++) {
                int ny = cy + (ay ? oyr : 0);
                for (int az = 0; az < nzl; az++) {
                    int nz = cz + (az ? ozr : 0);
                    int nc = (nx * GD + ny) * GD + nz;
                    unsigned st = nc ? off[nc - 1] : 0u;
                    unsigned en = off[nc];
                    for (unsigned s = st; s < en; s++) {
                        int j = (int)ids[s];
                        int dd = j - i;
                        if (dd > 2 || dd < -2) {
                            float dx = xi - P[3*j];
                            float dy = yi - P[3*j+1];
                            float dz = zi - P[3*j+2];
                            float d2 = dx*dx + dy*dy + dz*dz;
                            if (d2 < 2.25f) {
                                float v = 1.5f - sqrtf(d2 + EPSF);
                                acc += fmaxf(v, 0.0f) * mi * M[j];
                            }
                        }
                    }
                }
            }
        }
    }

    // ---- block reductions + atomics ----
    {
        float v[5] = {acc, bn, bd, lin, S};
        #pragma unroll
        for (int k = 0; k < 5; k++) {
            float w = warp_sum(v[k]);
            if ((tid & 31) == 0) swr[tid >> 5] = w;
            __syncthreads();
            if (tid == 0) {
                float s = 0.f;
                #pragma unroll
                for (int q = 0; q < NTHREADS / 32; q++) s += swr[q];
                if (s != 0.0f) {
                    if      (k == 0) atomicAdd(&g_clash, (double)s);
                    else if (k == 1) atomicAdd(&g_bn,    (double)s);
                    else if (k == 2) atomicAdd(&g_bd,    (double)s);
                    else if (k == 3) atomicAdd(&g_lin,   (double)s);
                    else             atomicAdd(&g_S[b],  (double)s);
                }
            }
            __syncthreads();
        }
    }

    // ---- last-block finalize (atomic ticket; no barrier) ----
    __threadfence();
    __shared__ bool is_last;
    if (tid == 0)
        is_last = (atomicAdd(&g_count, 1u) == (unsigned)(gridDim.x - 1));
    __syncthreads();
    if (is_last && tid == 0) {
        double pd = 0.0;
        #pragma unroll
        for (int bb = 0; bb < MAXB; bb++) {
            if (bb < B) { double Sb = g_S[bb]; pd += Sb * Sb; }
        }
        pd -= g_lin;
        double bond  = g_bn / (g_bd + 1e-8);
        double clash = g_clash / (pd + 1e-8);
        out[0] = (float)bond;
        out[1] = (float)clash;
        out[2] = (float)(bond + clash);
        g_clash = 0.0; g_bn = 0.0; g_bd = 0.0; g_lin = 0.0; g_count = 0u;
        #pragma unroll
        for (int bb = 0; bb < MAXB; bb++) g_S[bb] = 0.0;
    }
}

extern "C" void kernel_launch(void* const* d_in, const int* in_sizes, int n_in,
                              void* d_out, int out_size)
{
    const float* pos  = (const float*)d_in[0];
    const float* mask = (const float*)d_in[1];
    int B = in_sizes[1] / L_FIXED;
    if (B > MAXB) B = MAXB;

    violation_kernel<<<B * BPB, NTHREADS>>>(pos, mask, (float*)d_out, B);
}

// round 11
// speedup vs baseline: 3.9146x; 2.7154x over previous
#include <cuda_runtime.h>

#define L_FIXED 2048
#define TILE    128
#define JT      64                        // j sub-tile width
#define NT      16
#define NTP     136
#define MAXB    16
#define EPSF    1e-8f
#define CLASH2  2.25f
#define NTHREADS 256

typedef unsigned long long ull;

// ---- global accumulators (zero at load; finalize resets for graph replay) ----
__device__ double   g_clash = 0.0;
__device__ double   g_bn    = 0.0;
__device__ double   g_bd    = 0.0;
__device__ double   g_lin   = 0.0;
__device__ double   g_S[MAXB];
__device__ unsigned g_count = 0;

// ---- Blackwell packed f32x2 helpers ----
__device__ __forceinline__ ull pack2(float x) {
    ull r; asm("mov.b64 %0, {%1, %1};" : "=l"(r) : "f"(x)); return r;
}
__device__ __forceinline__ ull add2(ull a, ull b) {
    ull r; asm("add.rn.f32x2 %0, %1, %2;" : "=l"(r) : "l"(a), "l"(b)); return r;
}
__device__ __forceinline__ ull mul2(ull a, ull b) {
    ull r; asm("mul.rn.f32x2 %0, %1, %2;" : "=l"(r) : "l"(a), "l"(b)); return r;
}
__device__ __forceinline__ ull fma2(ull a, ull b, ull c) {
    ull r; asm("fma.rn.f32x2 %0, %1, %2, %3;" : "=l"(r) : "l"(a), "l"(b), "l"(c)); return r;
}
__device__ __forceinline__ void unpack2(ull v, float &lo, float &hi) {
    asm("mov.b64 {%0, %1}, %2;" : "=f"(lo), "=f"(hi) : "l"(v));
}
__device__ __forceinline__ float sqrt_apx(float x) {
    float r; asm("sqrt.approx.f32 %0, %1;" : "=f"(r) : "f"(x)); return r;
}
__device__ __forceinline__ float warp_sum(float v) {
    #pragma unroll
    for (int off = 16; off > 0; off >>= 1)
        v += __shfl_down_sync(0xffffffffu, v, off);
    return v;
}
__device__ __forceinline__ void displace(int i, float &X, float &Y, float &Z) {
    X = 3.0e7f + 16.0f * (float)i; Y = 0.0f; Z = 0.0f;
}

// ============================================================
// grid = (136 tile-pairs, B, 2 j-halves), block = 256.
// Block: 128 i-rows x 64 j-cols. 4 i-rows/thread, 8 j-slices of
// 8 j's (4 packed). LDS software-pipelined across the 4 k-iters.
// ============================================================
__global__ void __launch_bounds__(NTHREADS)
fused_violation_kernel(const float* __restrict__ pos,
                       const float* __restrict__ mask,
                       float* __restrict__ out, int B)
{
    const int p   = blockIdx.x;
    const int b   = blockIdx.y;
    const int zh  = blockIdx.z;
    const int tid = threadIdx.x;

    // closed-form triangular decode (exact at perfect squares)
    const int ti = (int)((33.0f - sqrtf(1089.0f - 8.0f * (float)p)) * 0.5f);
    const int tj = ti + (p - (ti * (33 - ti)) / 2);
    const int i0 = ti * TILE;
    const int j0 = tj * TILE + zh * JT;

    const float* P = pos  + (size_t)b * L_FIXED * 3;
    const float* M = mask + (size_t)b * L_FIXED;

    // ---- stage j sub-tile (negated, masked atoms displaced) ----
    __shared__ ull sjx[JT/2], sjy[JT/2], sjz[JT/2];
    if (tid < JT) {
        int j = j0 + tid;
        float mj = M[j];
        float X = P[3*j], Y = P[3*j+1], Z = P[3*j+2];
        if (mj == 0.0f) displace(j, X, Y, Z);
        ((float*)sjx)[tid] = -X;
        ((float*)sjy)[tid] = -Y;
        ((float*)sjz)[tid] = -Z;
    }

    // ---- per-thread i rows (4 consecutive) ----
    const int q = tid & 31;
    const int s = tid >> 5;               // 8 slices x 4 packed j
    const int ibase = i0 + 4 * q;
    ull xr[4], yr[4], zr[4];
    {
        const float4* P4 = (const float4*)(P + 3 * ibase);
        float4 v0 = P4[0], v1 = P4[1], v2 = P4[2];
        float c[12] = {v0.x, v0.y, v0.z, v0.w, v1.x, v1.y, v1.z, v1.w,
                       v2.x, v2.y, v2.z, v2.w};
        const float4 mv = *(const float4*)(M + ibase);
        float mm[4] = {mv.x, mv.y, mv.z, mv.w};
        #pragma unroll
        for (int r = 0; r < 4; r++) {
            int i = ibase + r;
            float X = c[3*r], Y = c[3*r+1], Z = c[3*r+2];
            if (mm[r] == 0.0f) displace(i, X, Y, Z);
            xr[r] = pack2(X); yr[r] = pack2(Y); zr[r] = pack2(Z);
        }
    }
    __syncthreads();

    float acc = 0.0f;
    const int kb = s * 4;
    const bool need_mask = (ti == tj) || (tj == ti + 1 && zh == 0);

    if (!need_mask) {
        // fast path: d2-only + vote-gated sqrt, LDS pipelined
        ull nx = sjx[kb], ny = sjy[kb], nz = sjz[kb];
        #pragma unroll
        for (int k = 0; k < 4; k++) {
            ull nx2, ny2, nz2;
            if (k < 3) { nx2 = sjx[kb+k+1]; ny2 = sjy[kb+k+1]; nz2 = sjz[kb+k+1]; }
            float lo[4], hi[4];
            #pragma unroll
            for (int r = 0; r < 4; r++) {
                ull dx = add2(xr[r], nx), dy = add2(yr[r], ny), dz = add2(zr[r], nz);
                ull d2 = fma2(dz, dz, fma2(dy, dy, mul2(dx, dx)));
                unpack2(d2, lo[r], hi[r]);
            }
            float mn = fminf(fminf(fminf(lo[0], hi[0]), fminf(lo[1], hi[1])),
                             fminf(fminf(lo[2], hi[2]), fminf(lo[3], hi[3])));
            if (__any_sync(0xffffffffu, mn < CLASH2)) {
                #pragma unroll
                for (int r = 0; r < 4; r++) {
                    acc += fmaxf(1.5f - sqrt_apx(lo[r] + EPSF), 0.0f);
                    acc += fmaxf(1.5f - sqrt_apx(hi[r] + EPSF), 0.0f);
                }
            }
            nx = nx2; ny = ny2; nz = nz2;
        }
    } else {
        // near-diagonal: branchless approx-sqrt + seq-sep masking
        const ull EPS2 = pack2(EPSF);
        ull nx = sjx[kb], ny = sjy[kb], nz = sjz[kb];
        #pragma unroll
        for (int k = 0; k < 4; k++) {
            ull nx2, ny2, nz2;
            if (k < 3) { nx2 = sjx[kb+k+1]; ny2 = sjy[kb+k+1]; nz2 = sjz[kb+k+1]; }
            int jlo = j0 + 2 * (kb + k), jhi = jlo + 1;
            #pragma unroll
            for (int r = 0; r < 4; r++) {
                int i = ibase + r;
                ull dx = add2(xr[r], nx), dy = add2(yr[r], ny), dz = add2(zr[r], nz);
                ull d2 = fma2(dz, dz, fma2(dy, dy, fma2(dx, dx, EPS2)));
                float lo, hi; unpack2(d2, lo, hi);
                float vl = fmaxf(1.5f - sqrt_apx(lo), 0.0f);
                float vh = fmaxf(1.5f - sqrt_apx(hi), 0.0f);
                if (jlo - i <= 2) vl = 0.0f;
                if (jhi - i <= 2) vh = 0.0f;
                acc += vl + vh;
            }
            nx = nx2; ny = ny2; nz = nz2;
        }
    }

    // ---- block reduction of clash partial ----
    __shared__ float swr[NTHREADS / 32];
    acc = warp_sum(acc);
    if ((tid & 31) == 0) swr[tid >> 5] = acc;
    __syncthreads();
    if (tid == 0) {
        float t = 0.0f;
        #pragma unroll
        for (int w = 0; w < NTHREADS / 32; w++) t += swr[w];
        if (t != 0.0f) atomicAdd(&g_clash, (double)t);
    }

    // ---- diagonal stats once per (tile-on-diagonal, batch): zh==0 only ----
    if (ti == tj && zh == 0) {
        float bn = 0.0f, bd = 0.0f, S = 0.0f, lin = 0.0f;
        if (tid < TILE) {
            int i = i0 + tid;
            float m = M[i];
            S = m; lin = m * m;
            if (i + 1 < L_FIXED) {
                float mj = M[i + 1];
                float dx = P[3*(i+1)]   - P[3*i];
                float dy = P[3*(i+1)+1] - P[3*i+1];
                float dz = P[3*(i+1)+2] - P[3*i+2];
                float d  = sqrtf(dx*dx + dy*dy + dz*dz + EPSF);
                float viol = fmaxf(fabsf(d - 3.8f) - 0.4f, 0.0f);
                float mm = m * mj;
                bd = mm; bn = viol * mm; lin += 2.0f * mm;
            }
            if (i + 2 < L_FIXED) lin += 2.0f * m * M[i + 2];
        }
        bn  = warp_sum(bn);
        bd  = warp_sum(bd);
        S   = warp_sum(S);
        lin = warp_sum(lin);
        __shared__ float sst[NTHREADS / 32][4];
        if ((tid & 31) == 0) {
            int w = tid >> 5;
            sst[w][0] = bn; sst[w][1] = bd; sst[w][2] = S; sst[w][3] = lin;
        }
        __syncthreads();
        if (tid == 0) {
            float tbn = 0, tbd = 0, tS = 0, tlin = 0;
            #pragma unroll
            for (int w = 0; w < NTHREADS / 32; w++) {
                tbn += sst[w][0]; tbd += sst[w][1];
                tS  += sst[w][2]; tlin += sst[w][3];
            }
            atomicAdd(&g_bn,  (double)tbn);
            atomicAdd(&g_bd,  (double)tbd);
            atomicAdd(&g_S[b], (double)tS);
            atomicAdd(&g_lin, (double)tlin);
        }
    }

    // ---- last-block finalize ----
    __threadfence();
    __shared__ bool is_last;
    if (tid == 0) {
        unsigned total = gridDim.x * gridDim.y * gridDim.z;
        is_last = (atomicAdd(&g_count, 1u) == total - 1u);
    }
    __syncthreads();
    if (is_last && tid == 0) {
        double pd = 0.0;
        #pragma unroll
        for (int bb = 0; bb < MAXB; bb++) {
            if (bb < B) { double Sb = *((volatile double*)&g_S[bb]); pd += Sb * Sb; }
        }
        pd -= *((volatile double*)&g_lin);
        double bn = *((volatile double*)&g_bn);
        double bd = *((volatile double*)&g_bd);
        double cl = *((volatile double*)&g_clash);
        double bond  = bn / (bd + 1e-8);
        double clash = 2.0 * cl / (pd + 1e-8);
        out[0] = (float)bond;
        out[1] = (float)clash;
        out[2] = (float)(bond + clash);
        g_clash = 0.0; g_bn = 0.0; g_bd = 0.0; g_lin = 0.0; g_count = 0u;
        #pragma unroll
        for (int bb = 0; bb < MAXB; bb++) g_S[bb] = 0.0;
    }
}

extern "C" void kernel_launch(void* const* d_in, const int* in_sizes, int n_in,
                              void* d_out, int out_size)
{
    const float* pos  = (const float*)d_in[0];
    const float* mask = (const float*)d_in[1];
    int B = in_sizes[1] / L_FIXED;
    if (B > MAXB) B = MAXB;

    dim3 grid(NTP, B, 2);
    fused_violation_kernel<<<grid, NTHREADS>>>(pos, mask, (float*)d_out, B);
}